// round 16
// baseline (speedup 1.0000x reference)
#include <cuda_runtime.h>
#include <cuda_bf16.h>
#include <math.h>

#define B_     4096
#define E_     64
#define D_     1024
#define KSPLIT 4
#define KCTA   (D_ / KSPLIT)   // 256 k per CTA
#define BKC    64              // k per chunk

// ---------------- scratch (__device__ globals; no allocs allowed) ----------
__device__ __align__(16) float         g_sinv[D_];
__device__ __align__(16) __nv_bfloat16 g_esb[E_ * D_];    // bf16 sinv*ek, [e][d]
__device__ __align__(16) __nv_bfloat16 g_ekTb[D_ * E_];   // bf16 ek^T, [d][e]
__device__ __align__(16) float         g_en[E_];
__device__ __align__(16) float         g_mean[D_];        // (1/64)*colsum(ek)
__device__ __align__(16) float         g_part[KSPLIT * B_ * E_];  // 4 MB
__device__ __align__(16) float         g_znp[KSPLIT * B_];

// ---------------- mma.sync helpers (base ISA, compute_103-safe) ------------
static __device__ __forceinline__ void ldsm_x4(unsigned& r0, unsigned& r1,
                                               unsigned& r2, unsigned& r3,
                                               unsigned addr) {
    asm volatile("ldmatrix.sync.aligned.m8n8.x4.shared.b16 {%0,%1,%2,%3}, [%4];"
                 : "=r"(r0), "=r"(r1), "=r"(r2), "=r"(r3) : "r"(addr));
}
static __device__ __forceinline__ void mma_bf16(float& c0, float& c1,
                                                float& c2, float& c3,
                                                unsigned a0, unsigned a1,
                                                unsigned a2, unsigned a3,
                                                unsigned b0, unsigned b1) {
    asm volatile(
        "mma.sync.aligned.m16n8k16.row.col.f32.bf16.bf16.f32 "
        "{%0,%1,%2,%3}, {%4,%5,%6,%7}, {%8,%9}, {%0,%1,%2,%3};"
        : "+f"(c0), "+f"(c1), "+f"(c2), "+f"(c3)
        : "r"(a0), "r"(a1), "r"(a2), "r"(a3), "r"(b0), "r"(b1));
}

#define PAD 72   // 144 B row stride -> 4-bank skew, conflict-free ldmatrix

// ---------------------------------------------------------------------------
// prep (+fused meank): blocks 0-63 per-expert prep; blocks 64-67 column mean.
// ---------------------------------------------------------------------------
__global__ __launch_bounds__(256) void prep_kernel(const float* __restrict__ ek,
                                                   const float* __restrict__ ls) {
    int tid = threadIdx.x;
    if (blockIdx.x >= E_) {
        int d = (blockIdx.x - E_) * 256 + tid;
        float acc = 0.f;
        #pragma unroll 8
        for (int e = 0; e < E_; e++) acc += ek[(size_t)e * D_ + d];
        g_mean[d] = acc * 0.015625f;
        return;
    }
    int e = blockIdx.x;
    float acc = 0.f;
    for (int d = tid; d < D_; d += 256) {
        float s = __expf(-ls[d]);
        if (e == 0) g_sinv[d] = s;
        float v = ek[e * D_ + d];
        float sv = s * v;
        g_esb[e * D_ + d] = __float2bfloat16(sv);
        g_ekTb[d * E_ + e] = __float2bfloat16(v);
        acc += sv * v;
    }
    __shared__ float red[8];
    #pragma unroll
    for (int o = 16; o > 0; o >>= 1) acc += __shfl_down_sync(0xffffffffu, acc, o);
    if ((tid & 31) == 0) red[tid >> 5] = acc;
    __syncthreads();
    if (tid == 0) {
        float s = 0.f;
        #pragma unroll
        for (int i = 0; i < 8; i++) s += red[i];
        g_en[e] = s;
    }
}

// ---------------------------------------------------------------------------
// k2: dist partial GEMM (unchanged from R15 — verified good).
// grid (B/128, KSPLIT) = (32,4) = 128 CTAs, 256 threads.
// ---------------------------------------------------------------------------
__global__ __launch_bounds__(256) void k2_mma(const float* __restrict__ z) {
    __shared__ __align__(16) __nv_bfloat16 sA[128 * PAD];
    __shared__ __align__(16) __nv_bfloat16 sB[64 * PAD];
    __shared__ __align__(16) float s_sinv[KCTA];

    const int tid = threadIdx.x;
    const int wid = tid >> 5, lane = tid & 31;
    const int r0 = blockIdx.x * 128;
    const int ks = blockIdx.y;
    const int kbase = ks * KCTA;

    for (int i = tid; i < KCTA / 4; i += 256)
        ((float4*)s_sinv)[i] = ((const float4*)(g_sinv + kbase))[i];

    const int ra = tid >> 1, h = tid & 1;
    const int rb = tid >> 2, q = tid & 3;
    const float* zrow = z + (size_t)(r0 + ra) * D_ + kbase + h * 32;
    const __nv_bfloat16* erow = g_esb + (size_t)rb * D_ + kbase + q * 16;

    float4 za[8];
    uint4  eb[2];
    {
        const float4* zs = (const float4*)zrow;
        #pragma unroll
        for (int u = 0; u < 8; u++) za[u] = zs[u];
        const uint4* es = (const uint4*)erow;
        eb[0] = es[0]; eb[1] = es[1];
    }

    const int l7 = lane & 7;
    const int aRow = wid * 16 + l7 + ((lane >> 3) & 1) * 8;
    const int aKo  = (lane >> 4) * 8;
    const int bNo  = l7 + (lane >> 4) * 8;
    const int bKo  = ((lane >> 3) & 1) * 8;
    const unsigned sA_addr = (unsigned)__cvta_generic_to_shared(sA);
    const unsigned sB_addr = (unsigned)__cvta_generic_to_shared(sB);

    float acc[8][4];
    #pragma unroll
    for (int j = 0; j < 8; j++)
        #pragma unroll
        for (int t = 0; t < 4; t++) acc[j][t] = 0.f;
    float zn = 0.f;

    for (int c = 0; c < KCTA / BKC; c++) {
        if (c) __syncthreads();
        {
            const float* sv = s_sinv + c * 64 + h * 32;
            #pragma unroll
            for (int u = 0; u < 8; u++) {
                float4 f = za[u];
                float4 s = *(const float4*)(sv + 4 * u);
                zn += s.x * f.x * f.x + s.y * f.y * f.y
                    + s.z * f.z * f.z + s.w * f.w * f.w;
                __nv_bfloat162 b01 = __floats2bfloat162_rn(f.x, f.y);
                __nv_bfloat162 b23 = __floats2bfloat162_rn(f.z, f.w);
                uint2 pk;
                pk.x = *reinterpret_cast<unsigned*>(&b01);
                pk.y = *reinterpret_cast<unsigned*>(&b23);
                *(uint2*)(&sA[ra * PAD + h * 32 + 4 * u]) = pk;
            }
            *(uint4*)(&sB[rb * PAD + q * 16])     = eb[0];
            *(uint4*)(&sB[rb * PAD + q * 16 + 8]) = eb[1];
        }
        __syncthreads();
        if (c < KCTA / BKC - 1) {
            const float4* zs = (const float4*)(zrow + (c + 1) * 64);
            #pragma unroll
            for (int u = 0; u < 8; u++) za[u] = zs[u];
            const uint4* es = (const uint4*)(erow + (c + 1) * 64);
            eb[0] = es[0]; eb[1] = es[1];
        }
        #pragma unroll
        for (int k16 = 0; k16 < 4; k16++) {
            const int k0 = k16 * 16;
            unsigned a0, a1, a2, a3;
            ldsm_x4(a0, a1, a2, a3, sA_addr + (aRow * PAD + k0 + aKo) * 2);
            #pragma unroll
            for (int g = 0; g < 4; g++) {
                unsigned b0, b1, b2, b3;
                ldsm_x4(b0, b1, b2, b3,
                        sB_addr + ((16 * g + bNo) * PAD + k0 + bKo) * 2);
                mma_bf16(acc[2*g][0], acc[2*g][1], acc[2*g][2], acc[2*g][3],
                         a0, a1, a2, a3, b0, b1);
                mma_bf16(acc[2*g+1][0], acc[2*g+1][1], acc[2*g+1][2], acc[2*g+1][3],
                         a0, a1, a2, a3, b2, b3);
            }
        }
    }

    zn += __shfl_xor_sync(0xffffffffu, zn, 1);
    if (h == 0) g_znp[ks * B_ + r0 + ra] = zn;

    const int gr = lane >> 2, tc = (lane & 3) * 2;
    const int mrow = r0 + wid * 16 + gr;
    float* dst = g_part + ((size_t)ks * B_ + mrow) * E_;
    #pragma unroll
    for (int j = 0; j < 8; j++) {
        *(float2*)(dst + 8 * j + tc)          = make_float2(acc[j][0], acc[j][1]);
        *(float2*)(dst + 8 * E_ + 8 * j + tc) = make_float2(acc[j][2], acc[j][3]);
    }
}

// ---------------------------------------------------------------------------
// k34: FUSED softmax + output GEMM. grid (B/128, D/128) = 256 CTAs, 256 thr.
// Phase 1: per-warp softmax for 16 rows (redundant across dc-blocks), writes
//          (w-1/64) bf16 straight into the MMA A-tile in smem; dc==0 slice
//          also writes out_sim.
// Phase 2: stage ek tile (128 d rows), 2 x 64-d MMA tiles, +mean epilogue.
// smem: sA 18432 + sB2 18432 = 36.9 KB.
// ---------------------------------------------------------------------------
__global__ __launch_bounds__(256) void k34_mma(float* __restrict__ out_sim,
                                               float* __restrict__ out_w) {
    __shared__ __align__(16) __nv_bfloat16 sA[128 * PAD];    // (w-1/64) tiles
    __shared__ __align__(16) __nv_bfloat16 sB2[128 * PAD];   // ek d-rows

    const int tid = threadIdx.x;
    const int wid = tid >> 5, lane = tid & 31;
    const int r0 = blockIdx.x * 128;
    const int dc0 = blockIdx.y * 128;

    // ---- Phase 1: softmax for rows wid*16 .. wid*16+15 ----
    {
        const float2 en = *(const float2*)(g_en + 2 * lane);
        #pragma unroll 2
        for (int rr = 0; rr < 16; rr++) {
            const int mloc = wid * 16 + rr;
            const int m = r0 + mloc;
            float dx = 0.f, dy = 0.f, zn = 0.f;
            #pragma unroll
            for (int ksp = 0; ksp < KSPLIT; ksp++) {
                float2 pp = *(const float2*)(g_part
                              + ((size_t)ksp * B_ + m) * E_ + 2 * lane);
                dx += pp.x; dy += pp.y;
                zn += g_znp[ksp * B_ + m];
            }
            float sim0 = 1.f / (1.f + zn + en.x - 2.f * dx);
            float sim1 = 1.f / (1.f + zn + en.y - 2.f * dy);
            if (blockIdx.y == 0)
                *(float2*)(out_sim + (size_t)m * E_ + 2 * lane)
                    = make_float2(sim0, sim1);

            float mx = fmaxf(sim0, sim1);
            #pragma unroll
            for (int o = 16; o; o >>= 1)
                mx = fmaxf(mx, __shfl_xor_sync(0xffffffffu, mx, o));
            float e0 = __expf(sim0 - mx), e1 = __expf(sim1 - mx);
            float s = e0 + e1;
            #pragma unroll
            for (int o = 16; o; o >>= 1)
                s += __shfl_xor_sync(0xffffffffu, s, o);
            float inv = 1.f / s;
            __nv_bfloat162 hh = __floats2bfloat162_rn(e0 * inv - 0.015625f,
                                                      e1 * inv - 0.015625f);
            *(unsigned*)(&sA[mloc * PAD + 2 * lane])
                = *reinterpret_cast<unsigned*>(&hh);
        }
    }

    // ---- stage ek tile: 128 d-rows x 64 e (2 thr/row, 4 uint4 each) ----
    {
        int r = tid >> 1, half = tid & 1;
        const __nv_bfloat16* src = g_ekTb + (size_t)(dc0 + r) * E_;
        #pragma unroll
        for (int u = 0; u < 4; u++) {
            int c16 = half * 4 + u;
            uint4 v = *(const uint4*)(src + c16 * 8);
            *(uint4*)(&sB2[r * PAD + c16 * 8]) = v;
        }
    }
    __syncthreads();

    // ---- Phase 2: MMA, 2 d-tiles of 64 ----
    const unsigned sA_addr = (unsigned)__cvta_generic_to_shared(sA);
    const unsigned sB_addr = (unsigned)__cvta_generic_to_shared(sB2);
    const int l7 = lane & 7;
    const int aRow = wid * 16 + l7 + ((lane >> 3) & 1) * 8;
    const int aKo  = (lane >> 4) * 8;
    const int bNo  = l7 + (lane >> 4) * 8;
    const int bKo  = ((lane >> 3) & 1) * 8;
    const int gr = lane >> 2, tc = (lane & 3) * 2;
    const int mrow = r0 + wid * 16 + gr;

    #pragma unroll
    for (int dt = 0; dt < 2; dt++) {
        float c[8][4];
        #pragma unroll
        for (int j = 0; j < 8; j++)
            #pragma unroll
            for (int t = 0; t < 4; t++) c[j][t] = 0.f;

        #pragma unroll
        for (int k16 = 0; k16 < 4; k16++) {
            const int k0 = k16 * 16;
            unsigned a0, a1, a2, a3;
            ldsm_x4(a0, a1, a2, a3, sA_addr + (aRow * PAD + k0 + aKo) * 2);
            #pragma unroll
            for (int g = 0; g < 4; g++) {
                unsigned b0, b1, b2, b3;
                ldsm_x4(b0, b1, b2, b3,
                        sB_addr + ((dt * 64 + 16 * g + bNo) * PAD + k0 + bKo) * 2);
                mma_bf16(c[2*g][0], c[2*g][1], c[2*g][2], c[2*g][3],
                         a0, a1, a2, a3, b0, b1);
                mma_bf16(c[2*g+1][0], c[2*g+1][1], c[2*g+1][2], c[2*g+1][3],
                         a0, a1, a2, a3, b2, b3);
            }
        }

        const int dc = dc0 + dt * 64;
        #pragma unroll
        for (int j = 0; j < 8; j++) {
            float2 mn = *(const float2*)(g_mean + dc + 8 * j + tc);
            *(float2*)(out_w + (size_t)mrow * D_ + dc + 8 * j + tc)
                = make_float2(c[j][0] + mn.x, c[j][1] + mn.y);
            *(float2*)(out_w + (size_t)(mrow + 8) * D_ + dc + 8 * j + tc)
                = make_float2(c[j][2] + mn.x, c[j][3] + mn.y);
        }
    }
}

// ---------------------------------------------------------------------------
extern "C" void kernel_launch(void* const* d_in, const int* in_sizes, int n_in,
                              void* d_out, int out_size) {
    const float* z  = (const float*)d_in[0];   // [B, D]
    const float* ek = (const float*)d_in[1];   // [E, D]
    const float* ls = (const float*)d_in[2];   // [D]
    float* out = (float*)d_out;
    float* out_sim = out;                      // [B, E]
    float* out_w   = out + (size_t)B_ * E_;    // [B, D]

    prep_kernel<<<E_ + D_ / 256, 256>>>(ek, ls);
    k2_mma<<<dim3(B_ / 128, KSPLIT), 256>>>(z);
    k34_mma<<<dim3(B_ / 128, D_ / 128), 256>>>(out_sim, out_w);
}

// round 17
// speedup vs baseline: 1.2164x; 1.2164x over previous
#include <cuda_runtime.h>
#include <cuda_bf16.h>
#include <math.h>

#define B_     4096
#define E_     64
#define D_     1024
#define KSPLIT 4
#define KCTA   (D_ / KSPLIT)   // 256 k per CTA
#define BKC    64              // k per chunk
#define NTILE  (D_ / 64)       // 16 prep tiles

// ---------------- scratch (__device__ globals; no allocs allowed) ----------
__device__ __align__(16) float         g_sinv[D_];
__device__ __align__(16) __nv_bfloat16 g_esb[E_ * D_];    // bf16 sinv*ek, [e][d]
__device__ __align__(16) __nv_bfloat16 g_ekTb[D_ * E_];   // bf16 ek^T, [d][e]
__device__ __align__(16) __nv_bfloat16 g_wres[B_ * E_];   // bf16 (w - 1/64)
__device__ __align__(16) float         g_enp[NTILE * E_]; // en partials per d-tile
__device__ __align__(16) float         g_mean[D_];        // (1/64)*colsum(ek)
__device__ __align__(16) float         g_part[KSPLIT * B_ * E_];  // 4 MB
__device__ __align__(16) float         g_znp[KSPLIT * B_];

// ---------------- mma.sync helpers (base ISA, compute_103-safe) ------------
static __device__ __forceinline__ void ldsm_x4(unsigned& r0, unsigned& r1,
                                               unsigned& r2, unsigned& r3,
                                               unsigned addr) {
    asm volatile("ldmatrix.sync.aligned.m8n8.x4.shared.b16 {%0,%1,%2,%3}, [%4];"
                 : "=r"(r0), "=r"(r1), "=r"(r2), "=r"(r3) : "r"(addr));
}
static __device__ __forceinline__ void mma_bf16(float& c0, float& c1,
                                                float& c2, float& c3,
                                                unsigned a0, unsigned a1,
                                                unsigned a2, unsigned a3,
                                                unsigned b0, unsigned b1) {
    asm volatile(
        "mma.sync.aligned.m16n8k16.row.col.f32.bf16.bf16.f32 "
        "{%0,%1,%2,%3}, {%4,%5,%6,%7}, {%8,%9}, {%0,%1,%2,%3};"
        : "+f"(c0), "+f"(c1), "+f"(c2), "+f"(c3)
        : "r"(a0), "r"(a1), "r"(a2), "r"(a3), "r"(b0), "r"(b1));
}

#define PAD 72   // 144 B row stride -> 4-bank skew, conflict-free ldmatrix

// ---------------------------------------------------------------------------
// prep: tiled 64e x 64d. Coalesced loads, smem transpose, coalesced stores.
// Writes g_sinv, g_esb, g_ekTb, g_mean; en as per-tile partials g_enp.
// grid NTILE=16, 256 threads. smem: 64*65*4 + 256 = 16.9 KB.
// ---------------------------------------------------------------------------
__global__ __launch_bounds__(256) void prep_kernel(const float* __restrict__ ek,
                                                   const float* __restrict__ ls) {
    __shared__ float s_tile[64][65];   // raw ek tile [e][d]
    __shared__ float s_sinv[64];

    const int tid = threadIdx.x;
    const int d0 = blockIdx.x * 64;

    if (tid < 64) {
        float s = __expf(-ls[d0 + tid]);
        s_sinv[tid] = s;
        g_sinv[d0 + tid] = s;
    }
    __syncthreads();

    // load ek tile + write esb + en partials. 16 rows/pass, 4 passes.
    const int rr = tid >> 4;        // row within pass
    const int cc = tid & 15;        // float4 column
    #pragma unroll
    for (int p = 0; p < 4; p++) {
        const int e = p * 16 + rr;
        float4 v = *(const float4*)(ek + (size_t)e * D_ + d0 + 4 * cc);
        s_tile[e][4 * cc + 0] = v.x;
        s_tile[e][4 * cc + 1] = v.y;
        s_tile[e][4 * cc + 2] = v.z;
        s_tile[e][4 * cc + 3] = v.w;
        float4 s = *(const float4*)(&s_sinv[4 * cc]);
        float4 sv = make_float4(s.x * v.x, s.y * v.y, s.z * v.z, s.w * v.w);
        __nv_bfloat162 b01 = __floats2bfloat162_rn(sv.x, sv.y);
        __nv_bfloat162 b23 = __floats2bfloat162_rn(sv.z, sv.w);
        uint2 pk;
        pk.x = *reinterpret_cast<unsigned*>(&b01);
        pk.y = *reinterpret_cast<unsigned*>(&b23);
        *(uint2*)(g_esb + (size_t)e * D_ + d0 + 4 * cc) = pk;
        // en partial for this e over this tile's 64 d
        float acc = sv.x * v.x + sv.y * v.y + sv.z * v.z + sv.w * v.w;
        acc += __shfl_xor_sync(0xffffffffu, acc, 1);
        acc += __shfl_xor_sync(0xffffffffu, acc, 2);
        acc += __shfl_xor_sync(0xffffffffu, acc, 4);
        acc += __shfl_xor_sync(0xffffffffu, acc, 8);
        if (cc == 0) g_enp[blockIdx.x * E_ + e] = acc;
    }
    __syncthreads();

    // write ekT coalesced: thread d=tid/4, segment cq=tid%4, 4 segs each.
    {
        const int d = tid >> 2, cq = tid & 3;
        #pragma unroll
        for (int u = 0; u < 4; u++) {
            int e0 = (cq * 4 + u) * 4;          // 4 e values per uint2
            __nv_bfloat162 b01 = __floats2bfloat162_rn(s_tile[e0 + 0][d],
                                                       s_tile[e0 + 1][d]);
            __nv_bfloat162 b23 = __floats2bfloat162_rn(s_tile[e0 + 2][d],
                                                       s_tile[e0 + 3][d]);
            uint2 pk;
            pk.x = *reinterpret_cast<unsigned*>(&b01);
            pk.y = *reinterpret_cast<unsigned*>(&b23);
            *(uint2*)(g_ekTb + (size_t)(d0 + d) * E_ + e0) = pk;
        }
    }

    // mean over e (tile spans all 64 e)
    if (tid < 64) {
        float acc = 0.f;
        #pragma unroll 16
        for (int e = 0; e < 64; e++) acc += s_tile[e][tid];
        g_mean[d0 + tid] = acc * 0.015625f;
    }
}

// ---------------------------------------------------------------------------
// k2: dist partial GEMM (unchanged from R15 — verified good).
// grid (B/128, KSPLIT) = (32,4) = 128 CTAs, 256 threads.
// ---------------------------------------------------------------------------
__global__ __launch_bounds__(256) void k2_mma(const float* __restrict__ z) {
    __shared__ __align__(16) __nv_bfloat16 sA[128 * PAD];
    __shared__ __align__(16) __nv_bfloat16 sB[64 * PAD];
    __shared__ __align__(16) float s_sinv[KCTA];

    const int tid = threadIdx.x;
    const int wid = tid >> 5, lane = tid & 31;
    const int r0 = blockIdx.x * 128;
    const int ks = blockIdx.y;
    const int kbase = ks * KCTA;

    for (int i = tid; i < KCTA / 4; i += 256)
        ((float4*)s_sinv)[i] = ((const float4*)(g_sinv + kbase))[i];

    const int ra = tid >> 1, h = tid & 1;
    const int rb = tid >> 2, q = tid & 3;
    const float* zrow = z + (size_t)(r0 + ra) * D_ + kbase + h * 32;
    const __nv_bfloat16* erow = g_esb + (size_t)rb * D_ + kbase + q * 16;

    float4 za[8];
    uint4  eb[2];
    {
        const float4* zs = (const float4*)zrow;
        #pragma unroll
        for (int u = 0; u < 8; u++) za[u] = zs[u];
        const uint4* es = (const uint4*)erow;
        eb[0] = es[0]; eb[1] = es[1];
    }

    const int l7 = lane & 7;
    const int aRow = wid * 16 + l7 + ((lane >> 3) & 1) * 8;
    const int aKo  = (lane >> 4) * 8;
    const int bNo  = l7 + (lane >> 4) * 8;
    const int bKo  = ((lane >> 3) & 1) * 8;
    const unsigned sA_addr = (unsigned)__cvta_generic_to_shared(sA);
    const unsigned sB_addr = (unsigned)__cvta_generic_to_shared(sB);

    float acc[8][4];
    #pragma unroll
    for (int j = 0; j < 8; j++)
        #pragma unroll
        for (int t = 0; t < 4; t++) acc[j][t] = 0.f;
    float zn = 0.f;

    for (int c = 0; c < KCTA / BKC; c++) {
        if (c) __syncthreads();
        {
            const float* sv = s_sinv + c * 64 + h * 32;
            #pragma unroll
            for (int u = 0; u < 8; u++) {
                float4 f = za[u];
                float4 s = *(const float4*)(sv + 4 * u);
                zn += s.x * f.x * f.x + s.y * f.y * f.y
                    + s.z * f.z * f.z + s.w * f.w * f.w;
                __nv_bfloat162 b01 = __floats2bfloat162_rn(f.x, f.y);
                __nv_bfloat162 b23 = __floats2bfloat162_rn(f.z, f.w);
                uint2 pk;
                pk.x = *reinterpret_cast<unsigned*>(&b01);
                pk.y = *reinterpret_cast<unsigned*>(&b23);
                *(uint2*)(&sA[ra * PAD + h * 32 + 4 * u]) = pk;
            }
            *(uint4*)(&sB[rb * PAD + q * 16])     = eb[0];
            *(uint4*)(&sB[rb * PAD + q * 16 + 8]) = eb[1];
        }
        __syncthreads();
        if (c < KCTA / BKC - 1) {
            const float4* zs = (const float4*)(zrow + (c + 1) * 64);
            #pragma unroll
            for (int u = 0; u < 8; u++) za[u] = zs[u];
            const uint4* es = (const uint4*)(erow + (c + 1) * 64);
            eb[0] = es[0]; eb[1] = es[1];
        }
        #pragma unroll
        for (int k16 = 0; k16 < 4; k16++) {
            const int k0 = k16 * 16;
            unsigned a0, a1, a2, a3;
            ldsm_x4(a0, a1, a2, a3, sA_addr + (aRow * PAD + k0 + aKo) * 2);
            #pragma unroll
            for (int g = 0; g < 4; g++) {
                unsigned b0, b1, b2, b3;
                ldsm_x4(b0, b1, b2, b3,
                        sB_addr + ((16 * g + bNo) * PAD + k0 + bKo) * 2);
                mma_bf16(acc[2*g][0], acc[2*g][1], acc[2*g][2], acc[2*g][3],
                         a0, a1, a2, a3, b0, b1);
                mma_bf16(acc[2*g+1][0], acc[2*g+1][1], acc[2*g+1][2], acc[2*g+1][3],
                         a0, a1, a2, a3, b2, b3);
            }
        }
    }

    zn += __shfl_xor_sync(0xffffffffu, zn, 1);
    if (h == 0) g_znp[ks * B_ + r0 + ra] = zn;

    const int gr = lane >> 2, tc = (lane & 3) * 2;
    const int mrow = r0 + wid * 16 + gr;
    float* dst = g_part + ((size_t)ks * B_ + mrow) * E_;
    #pragma unroll
    for (int j = 0; j < 8; j++) {
        *(float2*)(dst + 8 * j + tc)          = make_float2(acc[j][0], acc[j][1]);
        *(float2*)(dst + 8 * E_ + 8 * j + tc) = make_float2(acc[j][2], acc[j][3]);
    }
}

// ---------------------------------------------------------------------------
// k3: reduce partials (+ en partials) + similarity + softmax + wres
// ---------------------------------------------------------------------------
__global__ __launch_bounds__(256) void k3_softmax(float* __restrict__ out_sim) {
    const int lane = threadIdx.x & 31;
    const int m = blockIdx.x * 8 + (threadIdx.x >> 5);

    float enx = 0.f, eny = 0.f;
    #pragma unroll
    for (int t = 0; t < NTILE; t++) {
        float2 p = *(const float2*)(g_enp + t * E_ + 2 * lane);
        enx += p.x; eny += p.y;
    }

    float dx = 0.f, dy = 0.f, zn = 0.f;
    #pragma unroll
    for (int ksp = 0; ksp < KSPLIT; ksp++) {
        float2 pp = *(const float2*)(g_part + ((size_t)ksp * B_ + m) * E_ + 2 * lane);
        dx += pp.x; dy += pp.y;
        zn += g_znp[ksp * B_ + m];
    }
    float sim0 = 1.f / (1.f + zn + enx - 2.f * dx);
    float sim1 = 1.f / (1.f + zn + eny - 2.f * dy);
    *(float2*)(out_sim + (size_t)m * E_ + 2 * lane) = make_float2(sim0, sim1);

    float mx = fmaxf(sim0, sim1);
    #pragma unroll
    for (int o = 16; o; o >>= 1) mx = fmaxf(mx, __shfl_xor_sync(0xffffffffu, mx, o));
    float e0 = __expf(sim0 - mx), e1 = __expf(sim1 - mx);
    float s = e0 + e1;
    #pragma unroll
    for (int o = 16; o; o >>= 1) s += __shfl_xor_sync(0xffffffffu, s, o);
    float inv = 1.f / s;
    float w0 = e0 * inv - 0.015625f;   // exact (Sterbenz)
    float w1 = e1 * inv - 0.015625f;
    __nv_bfloat162 hh = __floats2bfloat162_rn(w0, w1);
    *(__nv_bfloat162*)(g_wres + (size_t)m * E_ + 2 * lane) = hh;
}

// ---------------------------------------------------------------------------
// k4: out_w = mean + wres @ ek. grid (B/64, D/64) = 1024 CTAs, 128 threads.
// CTA: 64m x 64d, K=E=64. Thin wide CTAs for wave-level latency hiding.
// smem: sA 64*72*2 + sB 64*72*2 = 18.4 KB.
// ---------------------------------------------------------------------------
__global__ __launch_bounds__(128) void k4_mma(float* __restrict__ out_w) {
    __shared__ __align__(16) __nv_bfloat16 sA[64 * PAD];
    __shared__ __align__(16) __nv_bfloat16 sB[64 * PAD];

    const int tid = threadIdx.x;
    const int wid = tid >> 5, lane = tid & 31;
    const int r0 = blockIdx.x * 64;
    const int dc = blockIdx.y * 64;

    {   // stage A: wres 64 rows x 8 uint4 (2 thr/row, 4 each)
        int r = tid >> 1, half = tid & 1;
        const __nv_bfloat16* src = g_wres + (size_t)(r0 + r) * E_;
        #pragma unroll
        for (int u = 0; u < 4; u++) {
            int c16 = half * 4 + u;
            uint4 v = *(const uint4*)(src + c16 * 8);
            *(uint4*)(&sA[r * PAD + c16 * 8]) = v;
        }
    }
    {   // stage B: ekT rows dc..dc+63 (2 thr/row, 4 each)
        int r = tid >> 1, half = tid & 1;
        const __nv_bfloat16* src = g_ekTb + (size_t)(dc + r) * E_;
        #pragma unroll
        for (int u = 0; u < 4; u++) {
            int c16 = half * 4 + u;
            uint4 v = *(const uint4*)(src + c16 * 8);
            *(uint4*)(&sB[r * PAD + c16 * 8]) = v;
        }
    }
    __syncthreads();

    const unsigned sA_addr = (unsigned)__cvta_generic_to_shared(sA);
    const unsigned sB_addr = (unsigned)__cvta_generic_to_shared(sB);
    const int l7 = lane & 7;
    const int aRow = wid * 16 + l7 + ((lane >> 3) & 1) * 8;
    const int aKo  = (lane >> 4) * 8;
    const int bNo  = l7 + (lane >> 4) * 8;
    const int bKo  = ((lane >> 3) & 1) * 8;

    float c[8][4];
    #pragma unroll
    for (int j = 0; j < 8; j++)
        #pragma unroll
        for (int t = 0; t < 4; t++) c[j][t] = 0.f;

    #pragma unroll
    for (int k16 = 0; k16 < 4; k16++) {
        const int k0 = k16 * 16;
        unsigned a0, a1, a2, a3;
        ldsm_x4(a0, a1, a2, a3, sA_addr + (aRow * PAD + k0 + aKo) * 2);
        #pragma unroll
        for (int g = 0; g < 4; g++) {
            unsigned b0, b1, b2, b3;
            ldsm_x4(b0, b1, b2, b3,
                    sB_addr + ((16 * g + bNo) * PAD + k0 + bKo) * 2);
            mma_bf16(c[2*g][0], c[2*g][1], c[2*g][2], c[2*g][3],
                     a0, a1, a2, a3, b0, b1);
            mma_bf16(c[2*g+1][0], c[2*g+1][1], c[2*g+1][2], c[2*g+1][3],
                     a0, a1, a2, a3, b2, b3);
        }
    }

    const int gr = lane >> 2, tc = (lane & 3) * 2;
    const int mrow = r0 + wid * 16 + gr;
    #pragma unroll
    for (int j = 0; j < 8; j++) {
        float2 mn = *(const float2*)(g_mean + dc + 8 * j + tc);
        *(float2*)(out_w + (size_t)mrow * D_ + dc + 8 * j + tc)
            = make_float2(c[j][0] + mn.x, c[j][1] + mn.y);
        *(float2*)(out_w + (size_t)(mrow + 8) * D_ + dc + 8 * j + tc)
            = make_float2(c[j][2] + mn.x, c[j][3] + mn.y);
    }
}

// ---------------------------------------------------------------------------
extern "C" void kernel_launch(void* const* d_in, const int* in_sizes, int n_in,
                              void* d_out, int out_size) {
    const float* z  = (const float*)d_in[0];   // [B, D]
    const float* ek = (const float*)d_in[1];   // [E, D]
    const float* ls = (const float*)d_in[2];   // [D]
    float* out = (float*)d_out;
    float* out_sim = out;                      // [B, E]
    float* out_w   = out + (size_t)B_ * E_;    // [B, D]

    prep_kernel<<<NTILE, 256>>>(ek, ls);
    k2_mma<<<dim3(B_ / 128, KSPLIT), 256>>>(z);
    k3_softmax<<<B_ / 8, 256>>>(out_sim);
    k4_mma<<<dim3(B_ / 64, D_ / 64), 128>>>(out_w);
}